// round 1
// baseline (speedup 1.0000x reference)
#include <cuda_runtime.h>
#include <math.h>

#define SMAX 2048
#define WDIM 1024

// ---------------- scratch (static device globals; no allocation) -------------
__device__ float g_H1[SMAX * WDIM];   // 8 MB
__device__ float g_H2[SMAX * WDIM];   // 8 MB
__device__ float g_HSUM[WDIM];        // column sums of h3
__device__ float g_M[64 * 64];        // combined bilinear matrix (interleaved layout)
__device__ float g_bsum;

__device__ __forceinline__ float gelu_f(float x) {
    // jax.nn.gelu default: tanh approximation
    float t = tanhf(0.7978845608028654f * (x + 0.044715f * x * x * x));
    return 0.5f * x * (1.0f + t);
}

// ---------------- bsum = (sum_s sources_s) . Wb + S*bb ----------------------
__global__ void k_bias(const float* __restrict__ src, const float* __restrict__ Wb,
                       const float* __restrict__ bb, int S) {
    __shared__ float red[256];
    int tid = threadIdx.x;
    float w0 = Wb[0], w1 = Wb[1], w2 = Wb[2], w3 = Wb[3];
    float acc = 0.f;
    for (int s = tid; s < S; s += 256) {
        float4 sv = *(const float4*)(src + 4 * s);
        acc += sv.x * w0 + sv.y * w1 + sv.z * w2 + sv.w * w3;
    }
    red[tid] = acc;
    __syncthreads();
    for (int off = 128; off > 0; off >>= 1) {
        if (tid < off) red[tid] += red[tid + off];
        __syncthreads();
    }
    if (tid == 0) g_bsum = red[0] + (float)S * bb[0];
}

// ---------------- layer 1: H1 = gelu(sources @ W1^T + b1), K=4 --------------
__global__ void k_layer1(const float* __restrict__ src, const float* __restrict__ W1,
                         const float* __restrict__ b1) {
    int idx = blockIdx.x * 256 + threadIdx.x;       // S*1024 threads
    int s = idx >> 10, o = idx & (WDIM - 1);
    float4 w  = *(const float4*)(W1 + 4 * o);
    float4 sv = *(const float4*)(src + 4 * s);
    float v = b1[o] + sv.x * w.x + sv.y * w.y + sv.z * w.z + sv.w * w.w;
    g_H1[idx] = gelu_f(v);
}

__global__ void k_zero() { g_HSUM[threadIdx.x] = 0.f; }   // launch <<<1,1024>>>

// ---------------- hidden GEMM: C = gelu(A @ B^T + bias) ---------------------
// A: SxK row-major (K contiguous), B: NxK row-major. BM=BN=64, BK=16, 256 thr,
// 4x4 per thread. SRC==1: A=g_H1 -> store g_H2. SRC==2: A=g_H2 -> column-sum
// reduce (fused hsum) into g_HSUM (no H3 store at all).
template <int SRC>
__global__ __launch_bounds__(256) void k_gemm(const float* __restrict__ B,
                                              const float* __restrict__ bias) {
    const float* A = (SRC == 1) ? g_H1 : g_H2;
    __shared__ float As[16][68];
    __shared__ float Bs[16][68];
    int tid = threadIdx.x;
    int tx = tid & 15, ty = tid >> 4;
    int m0 = blockIdx.y * 64, n0 = blockIdx.x * 64;
    int lrow = tid >> 2, lk = (tid & 3) * 4;
    const float* Ap = A + (m0 + lrow) * WDIM + lk;
    const float* Bp = B + (n0 + lrow) * WDIM + lk;
    float acc[4][4] = {};
    for (int k0 = 0; k0 < WDIM; k0 += 16) {
        float4 av = *(const float4*)(Ap + k0);
        float4 bv = *(const float4*)(Bp + k0);
        As[lk + 0][lrow] = av.x; As[lk + 1][lrow] = av.y;
        As[lk + 2][lrow] = av.z; As[lk + 3][lrow] = av.w;
        Bs[lk + 0][lrow] = bv.x; Bs[lk + 1][lrow] = bv.y;
        Bs[lk + 2][lrow] = bv.z; Bs[lk + 3][lrow] = bv.w;
        __syncthreads();
#pragma unroll
        for (int k = 0; k < 16; k++) {
            float4 a = *(const float4*)&As[k][ty * 4];
            float4 b = *(const float4*)&Bs[k][tx * 4];
            acc[0][0] += a.x * b.x; acc[0][1] += a.x * b.y; acc[0][2] += a.x * b.z; acc[0][3] += a.x * b.w;
            acc[1][0] += a.y * b.x; acc[1][1] += a.y * b.y; acc[1][2] += a.y * b.z; acc[1][3] += a.y * b.w;
            acc[2][0] += a.z * b.x; acc[2][1] += a.z * b.y; acc[2][2] += a.z * b.z; acc[2][3] += a.z * b.w;
            acc[3][0] += a.w * b.x; acc[3][1] += a.w * b.y; acc[3][2] += a.w * b.z; acc[3][3] += a.w * b.w;
        }
        __syncthreads();
    }
    float4 bb4 = *(const float4*)(bias + n0 + tx * 4);
    float ba[4] = {bb4.x, bb4.y, bb4.z, bb4.w};
    if (SRC == 1) {
#pragma unroll
        for (int i = 0; i < 4; i++) {
            float4 o;
            o.x = gelu_f(acc[i][0] + ba[0]);
            o.y = gelu_f(acc[i][1] + ba[1]);
            o.z = gelu_f(acc[i][2] + ba[2]);
            o.w = gelu_f(acc[i][3] + ba[3]);
            *(float4*)(g_H2 + (m0 + ty * 4 + i) * WDIM + n0 + tx * 4) = o;
        }
    } else {
        __shared__ float cs[64];
        if (tid < 64) cs[tid] = 0.f;
        __syncthreads();
        float p[4] = {0.f, 0.f, 0.f, 0.f};
#pragma unroll
        for (int i = 0; i < 4; i++)
#pragma unroll
            for (int j = 0; j < 4; j++)
                p[j] += gelu_f(acc[i][j] + ba[j]);
#pragma unroll
        for (int j = 0; j < 4; j++) atomicAdd(&cs[tx * 4 + j], p[j]);
        __syncthreads();
        if (tid < 64) atomicAdd(&g_HSUM[n0 + tid], cs[tid]);
    }
}

// ---------------- wsum GEMV + scatter into interleaved 64x64 M --------------
// wsum[c,i,j] = W4[row idx] . hsum + S*b4.  M layout: row 2i=cx_i, 2i+1=sx_i;
// col 2j=cy_j, 2j+1=sy_j. Channels: c0 cx*cy, c1 sx*sy, c2 cx*sy, c3 sx*cy.
__global__ void k_wsum(const float* __restrict__ W4, const float* __restrict__ b4,
                       float Sf) {
    int gw = (blockIdx.x * blockDim.x + threadIdx.x) >> 5;   // 0..4095
    int lane = threadIdx.x & 31;
    if (gw >= 4096) return;
    const float* wr = W4 + gw * WDIM;
    float acc = 0.f;
#pragma unroll 4
    for (int k = lane; k < WDIM; k += 32) acc += wr[k] * g_HSUM[k];
#pragma unroll
    for (int off = 16; off; off >>= 1) acc += __shfl_xor_sync(0xffffffffu, acc, off);
    if (lane == 0) {
        int c = gw >> 10, ij = gw & 1023, i = ij >> 5, j = ij & 31;
        int row = 2 * i + ((c == 1 || c == 3) ? 1 : 0);
        int col = 2 * j + ((c == 1 || c == 2) ? 1 : 0);
        g_M[row * 64 + col] = acc + Sf * b4[gw];
    }
}

// ---------------- Fourier evaluation: out_n = bsum + x^T M y ----------------
// Harmonics via angle-addition recurrence (1 sincosf per coordinate).
__global__ __launch_bounds__(128) void k_fourier(const float* __restrict__ r,
                                                 float* __restrict__ out, int NP) {
    __shared__ float sM[4096];
    for (int i = threadIdx.x; i < 4096; i += 128) sM[i] = g_M[i];
    __syncthreads();
    int n = blockIdx.x * 128 + threadIdx.x;
    if (n >= NP) return;
    float x = r[2 * n], y = r[2 * n + 1];
    const float w0 = 0.6283185307179586f;   // 2*pi/10
    float s1x, c1x, s1y, c1y;
    sincosf(w0 * x, &s1x, &c1x);
    sincosf(w0 * y, &s1y, &c1y);
    float xv[64];
    xv[0] = c1x; xv[1] = s1x;
    float cc = c1x, ss = s1x;
#pragma unroll
    for (int i = 1; i < 32; i++) {
        float nc = cc * c1x - ss * s1x;
        float ns = ss * c1x + cc * s1x;
        xv[2 * i] = nc; xv[2 * i + 1] = ns;
        cc = nc; ss = ns;
    }
    float acc = 0.f;
    float cy = c1y, sy = s1y;
#pragma unroll 1
    for (int jq = 0; jq < 16; jq++) {
        float cy2 = cy * c1y - sy * s1y;
        float sy2 = sy * c1y + cy * s1y;
        float t0 = 0.f, t1 = 0.f, t2 = 0.f, t3 = 0.f;
        const float* mp = sM + jq * 4;
#pragma unroll
        for (int i = 0; i < 64; i++) {
            float4 m = *(const float4*)(mp + i * 64);   // warp-broadcast LDS.128
            t0 += xv[i] * m.x; t1 += xv[i] * m.y;
            t2 += xv[i] * m.z; t3 += xv[i] * m.w;
        }
        acc += t0 * cy + t1 * sy + t2 * cy2 + t3 * sy2;
        float cy3 = cy2 * c1y - sy2 * s1y;
        float sy3 = sy2 * c1y + cy2 * s1y;
        cy = cy3; sy = sy3;
    }
    out[n] = g_bsum + acc;
}

// ---------------- launcher --------------------------------------------------
extern "C" void kernel_launch(void* const* d_in, const int* in_sizes, int n_in,
                              void* d_out, int out_size) {
    const float* sources = (const float*)d_in[0];
    const float* r       = (const float*)d_in[1];
    const float* W1      = (const float*)d_in[2];
    const float* b1      = (const float*)d_in[3];
    const float* W2      = (const float*)d_in[4];
    const float* b2      = (const float*)d_in[5];
    const float* W3      = (const float*)d_in[6];
    const float* b3      = (const float*)d_in[7];
    const float* W4      = (const float*)d_in[8];
    const float* b4      = (const float*)d_in[9];
    const float* Wb      = (const float*)d_in[10];
    const float* bb      = (const float*)d_in[11];
    float* out = (float*)d_out;

    int S  = in_sizes[0] / 4;          // 2048
    int NP = out_size;                 // 100000

    k_bias<<<1, 256>>>(sources, Wb, bb, S);
    k_layer1<<<(S * WDIM) / 256, 256>>>(sources, W1, b1);

    dim3 gg(WDIM / 64, S / 64);        // (16, 32)
    k_gemm<1><<<gg, 256>>>(W2, b2);    // H2 = gelu(H1 @ W2^T + b2)
    k_zero<<<1, 1024>>>();
    k_gemm<2><<<gg, 256>>>(W3, b3);    // hsum = colsum(gelu(H2 @ W3^T + b3))

    k_wsum<<<512, 256>>>(W4, b4, (float)S);

    int nb = (NP + 127) / 128;
    k_fourier<<<nb, 128>>>(r, out, NP);
}

// round 3
// speedup vs baseline: 2.3446x; 2.3446x over previous
#include <cuda_runtime.h>
#include <math.h>
#include <stdint.h>

#define SMAX 2048
#define WDIM 1024

// ---------------- scratch (static device globals; no allocation) -------------
__device__ float g_H1[SMAX * WDIM];     // 8 MB
__device__ float g_H2[SMAX * WDIM];     // 8 MB
__device__ float g_W2r[WDIM * WDIM];    // 4 MB (tf32-rounded W2)
__device__ float g_W3r[WDIM * WDIM];    // 4 MB (tf32-rounded W3)
__device__ float g_HSUM[WDIM];
__device__ float g_M[64 * 64];
__device__ float g_bsum;

__device__ __forceinline__ float gelu_f(float x) {
    float t = tanhf(0.7978845608028654f * (x + 0.044715f * x * x * x));
    return 0.5f * x * (1.0f + t);
}

__device__ __forceinline__ float tf32r(float x) {
    uint32_t u;
    asm("cvt.rna.tf32.f32 %0, %1;" : "=r"(u) : "f"(x));
    return __uint_as_float(u);
}

__device__ __forceinline__ void cp_async16(uint32_t dst, const void* src) {
    asm volatile("cp.async.cg.shared.global [%0], [%1], 16;\n" :: "r"(dst), "l"(src));
}

// ---------------- bsum + zero HSUM ------------------------------------------
__global__ void k_bias(const float* __restrict__ src, const float* __restrict__ Wb,
                       const float* __restrict__ bb, int S) {
    __shared__ float red[256];
    int tid = threadIdx.x;
    *(float4*)(g_HSUM + tid * 4) = make_float4(0.f, 0.f, 0.f, 0.f);
    float w0 = Wb[0], w1 = Wb[1], w2 = Wb[2], w3 = Wb[3];
    float acc = 0.f;
    for (int s = tid; s < S; s += 256) {
        float4 sv = *(const float4*)(src + 4 * s);
        acc += sv.x * w0 + sv.y * w1 + sv.z * w2 + sv.w * w3;
    }
    red[tid] = acc;
    __syncthreads();
    for (int off = 128; off > 0; off >>= 1) {
        if (tid < off) red[tid] += red[tid + off];
        __syncthreads();
    }
    if (tid == 0) g_bsum = red[0] + (float)S * bb[0];
}

// ---------------- pre-round weights to tf32 ---------------------------------
__global__ void k_round2(const float* __restrict__ W2, const float* __restrict__ W3) {
    int i = blockIdx.x * 256 + threadIdx.x;
    g_W2r[i] = tf32r(W2[i]);
    g_W3r[i] = tf32r(W3[i]);
}

// ---------------- layer 1: H1 = tf32(gelu(sources @ W1^T + b1)) -------------
__global__ void k_layer1(const float* __restrict__ src, const float* __restrict__ W1,
                         const float* __restrict__ b1) {
    int idx = blockIdx.x * 256 + threadIdx.x;
    int s = idx >> 10, o = idx & (WDIM - 1);
    float4 w  = *(const float4*)(W1 + 4 * o);
    float4 sv = *(const float4*)(src + 4 * s);
    float v = b1[o] + sv.x * w.x + sv.y * w.y + sv.z * w.z + sv.w * w.w;
    g_H1[idx] = tf32r(gelu_f(v));
}

// ---------------- tf32 tensor-core GEMM: C = gelu(A @ B^T + bias) -----------
// All heavy pointers (A, B) are resolved INSIDE device code (device globals
// cannot be passed as kernel args from the host launcher).
// SRC==1: A=g_H1, B=g_W2r -> store tf32(gelu) to g_H2.
// SRC==2: A=g_H2, B=g_W3r -> fused column-sum of gelu into g_HSUM (atomics).
template <int SRC>
__global__ __launch_bounds__(256) void k_gemm(const float* __restrict__ bias) {
    const float* A = (SRC == 1) ? g_H1 : g_H2;
    const float* B = (SRC == 1) ? g_W2r : g_W3r;
    __shared__ float As[2][128 * 20];    // [row][k], pad 20
    __shared__ float Bs[2][128 * 20];

    const int tid  = threadIdx.x;
    const int warp = tid >> 5, lane = tid & 31;
    const int quad = lane >> 2, qid = lane & 3;
    const int wm = warp >> 2, wn = warp & 3;       // 2 x 4 warps
    const int m0 = blockIdx.y * 128, n0 = blockIdx.x * 128;

    const int lrow = tid >> 2, lcol = (tid & 3) * 4;
    const float* Ap = A + (m0 + lrow) * WDIM + lcol;
    const float* Bp = B + (n0 + lrow) * WDIM + lcol;
    uint32_t sA = (uint32_t)__cvta_generic_to_shared(&As[0][0]) + (lrow * 20 + lcol) * 4;
    uint32_t sB = (uint32_t)__cvta_generic_to_shared(&Bs[0][0]) + (lrow * 20 + lcol) * 4;
    const uint32_t bufStride = 128 * 20 * 4;
    const uint32_t rowStride = 64 * 20 * 4;

    float acc[4][4][4];
#pragma unroll
    for (int i = 0; i < 4; i++)
#pragma unroll
        for (int j = 0; j < 4; j++)
#pragma unroll
            for (int q = 0; q < 4; q++) acc[i][j][q] = 0.f;

    // preload tile 0
    cp_async16(sA, Ap);
    cp_async16(sA + rowStride, Ap + 64 * WDIM);
    cp_async16(sB, Bp);
    cp_async16(sB + rowStride, Bp + 64 * WDIM);
    asm volatile("cp.async.commit_group;\n");

    const int NT = WDIM / 16;
    for (int kt = 0; kt < NT; kt++) {
        int cur = kt & 1;
        if (kt + 1 < NT) {
            const float* Ap2 = Ap + (kt + 1) * 16;
            const float* Bp2 = Bp + (kt + 1) * 16;
            uint32_t dA = sA + (1 - cur) * bufStride;
            uint32_t dB = sB + (1 - cur) * bufStride;
            cp_async16(dA, Ap2);
            cp_async16(dA + rowStride, Ap2 + 64 * WDIM);
            cp_async16(dB, Bp2);
            cp_async16(dB + rowStride, Bp2 + 64 * WDIM);
            asm volatile("cp.async.commit_group;\n");
            asm volatile("cp.async.wait_group 1;\n");
        } else {
            asm volatile("cp.async.wait_group 0;\n");
        }
        __syncthreads();

        const float* as = &As[cur][0];
        const float* bs = &Bs[cur][0];
#pragma unroll
        for (int ks = 0; ks < 2; ks++) {
            int kk = ks * 8;
            uint32_t a[4][4], b[4][2];
#pragma unroll
            for (int mt = 0; mt < 4; mt++) {
                int r = wm * 64 + mt * 16 + quad;
                a[mt][0] = __float_as_uint(as[r * 20 + kk + qid]);
                a[mt][1] = __float_as_uint(as[(r + 8) * 20 + kk + qid]);
                a[mt][2] = __float_as_uint(as[r * 20 + kk + qid + 4]);
                a[mt][3] = __float_as_uint(as[(r + 8) * 20 + kk + qid + 4]);
            }
#pragma unroll
            for (int nt = 0; nt < 4; nt++) {
                int n = wn * 32 + nt * 8 + quad;
                b[nt][0] = __float_as_uint(bs[n * 20 + kk + qid]);
                b[nt][1] = __float_as_uint(bs[n * 20 + kk + qid + 4]);
            }
#pragma unroll
            for (int mt = 0; mt < 4; mt++)
#pragma unroll
                for (int nt = 0; nt < 4; nt++) {
                    asm volatile(
                        "mma.sync.aligned.m16n8k8.row.col.f32.tf32.tf32.f32 "
                        "{%0,%1,%2,%3}, {%4,%5,%6,%7}, {%8,%9}, {%0,%1,%2,%3};\n"
                        : "+f"(acc[mt][nt][0]), "+f"(acc[mt][nt][1]),
                          "+f"(acc[mt][nt][2]), "+f"(acc[mt][nt][3])
                        : "r"(a[mt][0]), "r"(a[mt][1]), "r"(a[mt][2]), "r"(a[mt][3]),
                          "r"(b[nt][0]), "r"(b[nt][1]));
                }
        }
        __syncthreads();
    }

    // epilogue
    if (SRC == 1) {
#pragma unroll
        for (int mt = 0; mt < 4; mt++) {
            int mrow = m0 + wm * 64 + mt * 16 + quad;
#pragma unroll
            for (int nt = 0; nt < 4; nt++) {
                int ncol = n0 + wn * 32 + nt * 8 + 2 * qid;
                float b0 = bias[ncol], b1 = bias[ncol + 1];
                float2 o0, o1;
                o0.x = tf32r(gelu_f(acc[mt][nt][0] + b0));
                o0.y = tf32r(gelu_f(acc[mt][nt][1] + b1));
                o1.x = tf32r(gelu_f(acc[mt][nt][2] + b0));
                o1.y = tf32r(gelu_f(acc[mt][nt][3] + b1));
                *(float2*)(g_H2 + mrow * WDIM + ncol) = o0;
                *(float2*)(g_H2 + (mrow + 8) * WDIM + ncol) = o1;
            }
        }
    } else {
        float colacc[4][2];
#pragma unroll
        for (int nt = 0; nt < 4; nt++) { colacc[nt][0] = 0.f; colacc[nt][1] = 0.f; }
#pragma unroll
        for (int nt = 0; nt < 4; nt++) {
            int ncol = n0 + wn * 32 + nt * 8 + 2 * qid;
            float b0 = bias[ncol], b1 = bias[ncol + 1];
#pragma unroll
            for (int mt = 0; mt < 4; mt++) {
                colacc[nt][0] += gelu_f(acc[mt][nt][0] + b0) + gelu_f(acc[mt][nt][2] + b0);
                colacc[nt][1] += gelu_f(acc[mt][nt][1] + b1) + gelu_f(acc[mt][nt][3] + b1);
            }
        }
#pragma unroll
        for (int nt = 0; nt < 4; nt++)
#pragma unroll
            for (int c = 0; c < 2; c++) {
                float v = colacc[nt][c];
                v += __shfl_xor_sync(0xffffffffu, v, 4);
                v += __shfl_xor_sync(0xffffffffu, v, 8);
                v += __shfl_xor_sync(0xffffffffu, v, 16);
                colacc[nt][c] = v;
            }
        if (quad == 0) {
#pragma unroll
            for (int nt = 0; nt < 4; nt++) {
                int ncol = n0 + wn * 32 + nt * 8 + 2 * qid;
                atomicAdd(&g_HSUM[ncol], colacc[nt][0]);
                atomicAdd(&g_HSUM[ncol + 1], colacc[nt][1]);
            }
        }
    }
}

// ---------------- wsum GEMV + scatter into interleaved 64x64 M --------------
__global__ void k_wsum(const float* __restrict__ W4, const float* __restrict__ b4,
                       float Sf) {
    int gw = (blockIdx.x * blockDim.x + threadIdx.x) >> 5;   // 0..4095
    int lane = threadIdx.x & 31;
    if (gw >= 4096) return;
    const float* wr = W4 + gw * WDIM;
    float acc = 0.f;
#pragma unroll 4
    for (int k = lane; k < WDIM; k += 32) acc += wr[k] * g_HSUM[k];
#pragma unroll
    for (int off = 16; off; off >>= 1) acc += __shfl_xor_sync(0xffffffffu, acc, off);
    if (lane == 0) {
        int c = gw >> 10, ij = gw & 1023, i = ij >> 5, j = ij & 31;
        int row = 2 * i + ((c == 1 || c == 3) ? 1 : 0);
        int col = 2 * j + ((c == 1 || c == 2) ? 1 : 0);
        g_M[row * 64 + col] = acc + Sf * b4[gw];
    }
}

// ---------------- Fourier evaluation: out_n = bsum + x^T M y ----------------
__global__ __launch_bounds__(128) void k_fourier(const float* __restrict__ r,
                                                 float* __restrict__ out, int NP) {
    __shared__ float sM[4096];
    for (int i = threadIdx.x; i < 4096; i += 128) sM[i] = g_M[i];
    __syncthreads();
    int n = blockIdx.x * 128 + threadIdx.x;
    if (n >= NP) return;
    float x = r[2 * n], y = r[2 * n + 1];
    const float w0 = 0.6283185307179586f;
    float s1x, c1x, s1y, c1y;
    sincosf(w0 * x, &s1x, &c1x);
    sincosf(w0 * y, &s1y, &c1y);
    float xv[64];
    xv[0] = c1x; xv[1] = s1x;
    float cc = c1x, ss = s1x;
#pragma unroll
    for (int i = 1; i < 32; i++) {
        float nc = cc * c1x - ss * s1x;
        float ns = ss * c1x + cc * s1x;
        xv[2 * i] = nc; xv[2 * i + 1] = ns;
        cc = nc; ss = ns;
    }
    float acc = 0.f;
    float cy = c1y, sy = s1y;
#pragma unroll 1
    for (int jq = 0; jq < 16; jq++) {
        float cy2 = cy * c1y - sy * s1y;
        float sy2 = sy * c1y + cy * s1y;
        float t0 = 0.f, t1 = 0.f, t2 = 0.f, t3 = 0.f;
        const float* mp = sM + jq * 4;
#pragma unroll
        for (int i = 0; i < 64; i++) {
            float4 m = *(const float4*)(mp + i * 64);
            t0 += xv[i] * m.x; t1 += xv[i] * m.y;
            t2 += xv[i] * m.z; t3 += xv[i] * m.w;
        }
        acc += t0 * cy + t1 * sy + t2 * cy2 + t3 * sy2;
        float cy3 = cy2 * c1y - sy2 * s1y;
        float sy3 = sy2 * c1y + cy2 * s1y;
        cy = cy3; sy = sy3;
    }
    out[n] = g_bsum + acc;
}

// ---------------- launcher --------------------------------------------------
extern "C" void kernel_launch(void* const* d_in, const int* in_sizes, int n_in,
                              void* d_out, int out_size) {
    const float* sources = (const float*)d_in[0];
    const float* r       = (const float*)d_in[1];
    const float* W1      = (const float*)d_in[2];
    const float* b1      = (const float*)d_in[3];
    const float* W2      = (const float*)d_in[4];
    const float* b2      = (const float*)d_in[5];
    const float* W3      = (const float*)d_in[6];
    const float* b3      = (const float*)d_in[7];
    const float* W4      = (const float*)d_in[8];
    const float* b4      = (const float*)d_in[9];
    const float* Wb      = (const float*)d_in[10];
    const float* bb      = (const float*)d_in[11];
    float* out = (float*)d_out;

    int S  = in_sizes[0] / 4;          // 2048
    int NP = out_size;                 // 100000

    k_bias<<<1, 256>>>(sources, Wb, bb, S);
    k_round2<<<(WDIM * WDIM) / 256, 256>>>(W2, W3);
    k_layer1<<<(S * WDIM) / 256, 256>>>(sources, W1, b1);

    dim3 gg(WDIM / 128, S / 128);      // (8, 16)
    k_gemm<1><<<gg, 256>>>(b2);
    k_gemm<2><<<gg, 256>>>(b3);

    k_wsum<<<512, 256>>>(W4, b4, (float)S);

    int nb = (NP + 127) / 128;
    k_fourier<<<nb, 128>>>(r, out, NP);
}

// round 4
// speedup vs baseline: 2.6090x; 1.1128x over previous
#include <cuda_runtime.h>
#include <math.h>
#include <stdint.h>

#define SMAX 2048
#define WDIM 1024

// ---------------- scratch (static device globals; no allocation) -------------
__device__ float g_H1[SMAX * WDIM];     // 8 MB
__device__ float g_H2[SMAX * WDIM];     // 8 MB
__device__ float g_W2r[WDIM * WDIM];    // 4 MB (tf32-rounded W2)
__device__ float g_W3r[WDIM * WDIM];    // 4 MB (tf32-rounded W3)
__device__ float g_HSUM[WDIM];
__device__ float g_M[64 * 64];
__device__ float g_bsum;

__device__ __forceinline__ float gelu_f(float x) {
    float t = tanhf(0.7978845608028654f * (x + 0.044715f * x * x * x));
    return 0.5f * x * (1.0f + t);
}

__device__ __forceinline__ float tf32r(float x) {
    uint32_t u;
    asm("cvt.rna.tf32.f32 %0, %1;" : "=r"(u) : "f"(x));
    return __uint_as_float(u);
}

__device__ __forceinline__ void cp_async16(uint32_t dst, const void* src) {
    asm volatile("cp.async.cg.shared.global [%0], [%1], 16;\n" :: "r"(dst), "l"(src));
}

__device__ __forceinline__ unsigned long long pk2(float a, float b) {
    unsigned long long d;
    asm("mov.b64 %0, {%1, %2};" : "=l"(d) : "f"(a), "f"(b));
    return d;
}
__device__ __forceinline__ void fma2(unsigned long long& d, unsigned long long a,
                                     unsigned long long b) {
    asm("fma.rn.f32x2 %0, %1, %2, %0;" : "+l"(d) : "l"(a), "l"(b));
}

// ---------------- fused prep: bsum+hsum-zero | W2/W3 tf32 round | layer1 ----
__global__ void k_prep(const float* __restrict__ src, const float* __restrict__ W1,
                       const float* __restrict__ b1, const float* __restrict__ W2,
                       const float* __restrict__ W3, const float* __restrict__ Wb,
                       const float* __restrict__ bb, int S) {
    int bid = blockIdx.x;
    int tid = threadIdx.x;
    if (bid < 4096) {                       // weight rounding: 2 x 1M elements
        int i = bid * 256 + tid;
        g_W2r[i] = tf32r(W2[i]);
        g_W3r[i] = tf32r(W3[i]);
    } else if (bid < 12288) {               // layer 1
        int idx = (bid - 4096) * 256 + tid;
        int s = idx >> 10, o = idx & (WDIM - 1);
        float4 w  = *(const float4*)(W1 + 4 * o);
        float4 sv = *(const float4*)(src + 4 * s);
        float v = b1[o] + sv.x * w.x + sv.y * w.y + sv.z * w.z + sv.w * w.w;
        g_H1[idx] = tf32r(gelu_f(v));
    } else {                                // bias reduce + zero HSUM
        __shared__ float red[256];
        *(float4*)(g_HSUM + tid * 4) = make_float4(0.f, 0.f, 0.f, 0.f);
        float w0 = Wb[0], w1 = Wb[1], w2 = Wb[2], w3 = Wb[3];
        float acc = 0.f;
        for (int s = tid; s < S; s += 256) {
            float4 sv = *(const float4*)(src + 4 * s);
            acc += sv.x * w0 + sv.y * w1 + sv.z * w2 + sv.w * w3;
        }
        red[tid] = acc;
        __syncthreads();
        for (int off = 128; off > 0; off >>= 1) {
            if (tid < off) red[tid] += red[tid + off];
            __syncthreads();
        }
        if (tid == 0) g_bsum = red[0] + (float)S * bb[0];
    }
}

// ---------------- tf32 tensor-core GEMM: C = gelu(A @ B^T + bias) -----------
// CTA tile 128x64, 128 threads = 4 warps (2x2), warp tile 64x32.
// 3-stage cp.async pipeline, BK=16. grid (16 N, 16 M) = 256 CTAs.
// SRC==1: A=g_H1, B=g_W2r -> store tf32(gelu) to g_H2.
// SRC==2: A=g_H2, B=g_W3r -> fused column-sum of gelu into g_HSUM.
#define GP 20   // smem pitch in floats

__device__ __forceinline__ void load_stage(const float* __restrict__ Ab,
                                           const float* __restrict__ Bb,
                                           uint32_t sa, uint32_t sb, int tid) {
#pragma unroll
    for (int i = 0; i < 4; i++) {
        int slot = tid + 128 * i, row = slot >> 2, cg = slot & 3;
        cp_async16(sa + (row * GP + cg * 4) * 4, Ab + row * WDIM + cg * 4);
    }
#pragma unroll
    for (int i = 0; i < 2; i++) {
        int slot = tid + 128 * i, row = slot >> 2, cg = slot & 3;
        cp_async16(sb + (row * GP + cg * 4) * 4, Bb + row * WDIM + cg * 4);
    }
}

template <int SRC>
__global__ __launch_bounds__(128) void k_gemm(const float* __restrict__ bias) {
    const float* A = (SRC == 1) ? g_H1 : g_H2;
    const float* B = (SRC == 1) ? g_W2r : g_W3r;
    __shared__ __align__(16) float As[3][128 * GP];
    __shared__ __align__(16) float Bs[3][64 * GP];

    const int tid  = threadIdx.x;
    const int warp = tid >> 5, lane = tid & 31;
    const int quad = lane >> 2, qid = lane & 3;
    const int wm = (warp >> 1) * 64, wn = (warp & 1) * 32;
    const int m0 = blockIdx.y * 128, n0 = blockIdx.x * 64;

    const float* Abase = A + m0 * WDIM;
    const float* Bbase = B + n0 * WDIM;
    const uint32_t sa0 = (uint32_t)__cvta_generic_to_shared(&As[0][0]);
    const uint32_t sb0 = (uint32_t)__cvta_generic_to_shared(&Bs[0][0]);
    const uint32_t saStride = 128 * GP * 4, sbStride = 64 * GP * 4;

    float acc[4][4][4];
#pragma unroll
    for (int i = 0; i < 4; i++)
#pragma unroll
        for (int j = 0; j < 4; j++)
#pragma unroll
            for (int q = 0; q < 4; q++) acc[i][j][q] = 0.f;

    // prologue: stages 0,1
    load_stage(Abase + 0 * 16, Bbase + 0 * 16, sa0, sb0, tid);
    asm volatile("cp.async.commit_group;\n");
    load_stage(Abase + 1 * 16, Bbase + 1 * 16, sa0 + saStride, sb0 + sbStride, tid);
    asm volatile("cp.async.commit_group;\n");

    const int NT = WDIM / 16;           // 64
    int s = 0;
    for (int kt = 0; kt < NT; kt++) {
        asm volatile("cp.async.wait_group 1;\n");
        __syncthreads();                 // stage kt visible; all warps done with kt-1
        if (kt + 2 < NT) {
            int s2 = (s + 2 >= 3) ? s - 1 : s + 2;
            load_stage(Abase + (kt + 2) * 16, Bbase + (kt + 2) * 16,
                       sa0 + s2 * saStride, sb0 + s2 * sbStride, tid);
        }
        asm volatile("cp.async.commit_group;\n");

        const float* as = &As[s][0];
        const float* bs = &Bs[s][0];
#pragma unroll
        for (int ks = 0; ks < 2; ks++) {
            int kk = ks * 8;
            uint32_t a[4][4], b[4][2];
#pragma unroll
            for (int mt = 0; mt < 4; mt++) {
                int r = wm + mt * 16 + quad;
                a[mt][0] = __float_as_uint(as[r * GP + kk + qid]);
                a[mt][1] = __float_as_uint(as[(r + 8) * GP + kk + qid]);
                a[mt][2] = __float_as_uint(as[r * GP + kk + qid + 4]);
                a[mt][3] = __float_as_uint(as[(r + 8) * GP + kk + qid + 4]);
            }
#pragma unroll
            for (int nt = 0; nt < 4; nt++) {
                int n = wn + nt * 8 + quad;
                b[nt][0] = __float_as_uint(bs[n * GP + kk + qid]);
                b[nt][1] = __float_as_uint(bs[n * GP + kk + qid + 4]);
            }
#pragma unroll
            for (int mt = 0; mt < 4; mt++)
#pragma unroll
                for (int nt = 0; nt < 4; nt++) {
                    asm volatile(
                        "mma.sync.aligned.m16n8k8.row.col.f32.tf32.tf32.f32 "
                        "{%0,%1,%2,%3}, {%4,%5,%6,%7}, {%8,%9}, {%0,%1,%2,%3};\n"
                        : "+f"(acc[mt][nt][0]), "+f"(acc[mt][nt][1]),
                          "+f"(acc[mt][nt][2]), "+f"(acc[mt][nt][3])
                        : "r"(a[mt][0]), "r"(a[mt][1]), "r"(a[mt][2]), "r"(a[mt][3]),
                          "r"(b[nt][0]), "r"(b[nt][1]));
                }
        }
        s = (s + 1 >= 3) ? 0 : s + 1;
    }

    // epilogue
    if (SRC == 1) {
#pragma unroll
        for (int mt = 0; mt < 4; mt++) {
            int mrow = m0 + wm + mt * 16 + quad;
#pragma unroll
            for (int nt = 0; nt < 4; nt++) {
                int ncol = n0 + wn + nt * 8 + 2 * qid;
                float b0 = bias[ncol], b1 = bias[ncol + 1];
                float2 o0, o1;
                o0.x = tf32r(gelu_f(acc[mt][nt][0] + b0));
                o0.y = tf32r(gelu_f(acc[mt][nt][1] + b1));
                o1.x = tf32r(gelu_f(acc[mt][nt][2] + b0));
                o1.y = tf32r(gelu_f(acc[mt][nt][3] + b1));
                *(float2*)(g_H2 + mrow * WDIM + ncol) = o0;
                *(float2*)(g_H2 + (mrow + 8) * WDIM + ncol) = o1;
            }
        }
    } else {
        float colacc[4][2];
#pragma unroll
        for (int nt = 0; nt < 4; nt++) { colacc[nt][0] = 0.f; colacc[nt][1] = 0.f; }
#pragma unroll
        for (int nt = 0; nt < 4; nt++) {
            int ncol = n0 + wn + nt * 8 + 2 * qid;
            float b0 = bias[ncol], b1 = bias[ncol + 1];
#pragma unroll
            for (int mt = 0; mt < 4; mt++) {
                colacc[nt][0] += gelu_f(acc[mt][nt][0] + b0) + gelu_f(acc[mt][nt][2] + b0);
                colacc[nt][1] += gelu_f(acc[mt][nt][1] + b1) + gelu_f(acc[mt][nt][3] + b1);
            }
        }
#pragma unroll
        for (int nt = 0; nt < 4; nt++)
#pragma unroll
            for (int c = 0; c < 2; c++) {
                float v = colacc[nt][c];
                v += __shfl_xor_sync(0xffffffffu, v, 4);
                v += __shfl_xor_sync(0xffffffffu, v, 8);
                v += __shfl_xor_sync(0xffffffffu, v, 16);
                colacc[nt][c] = v;
            }
        if (quad == 0) {
#pragma unroll
            for (int nt = 0; nt < 4; nt++) {
                int ncol = n0 + wn + nt * 8 + 2 * qid;
                atomicAdd(&g_HSUM[ncol], colacc[nt][0]);
                atomicAdd(&g_HSUM[ncol + 1], colacc[nt][1]);
            }
        }
    }
}

// ---------------- wsum GEMV + scatter into interleaved 64x64 M --------------
__global__ void k_wsum(const float* __restrict__ W4, const float* __restrict__ b4,
                       float Sf) {
    int gw = (blockIdx.x * blockDim.x + threadIdx.x) >> 5;   // 0..4095
    int lane = threadIdx.x & 31;
    if (gw >= 4096) return;
    const float* wr = W4 + gw * WDIM;
    float acc = 0.f;
#pragma unroll 4
    for (int k = lane; k < WDIM; k += 32) acc += wr[k] * g_HSUM[k];
#pragma unroll
    for (int off = 16; off; off >>= 1) acc += __shfl_xor_sync(0xffffffffu, acc, off);
    if (lane == 0) {
        int c = gw >> 10, ij = gw & 1023, i = ij >> 5, j = ij & 31;
        int row = 2 * i + ((c == 1 || c == 3) ? 1 : 0);
        int col = 2 * j + ((c == 1 || c == 2) ? 1 : 0);
        g_M[row * 64 + col] = acc + Sf * b4[gw];
    }
}

// ---------------- Fourier evaluation (f32x2 packed math) --------------------
// out_n = bsum + x^T M y.  x-harmonics pre-packed duplicated (v,v) as u64;
// per 4 columns: 1 LDS.v2.b64 + 2 FFMA2 (vs 4 FFMA) -> 2x FMA-pipe rate.
__global__ __launch_bounds__(128) void k_fourier(const float* __restrict__ r,
                                                 float* __restrict__ out, int NP) {
    __shared__ __align__(16) float sM[4096];
    for (int i = threadIdx.x; i < 4096; i += 128) sM[i] = g_M[i];
    __syncthreads();
    int n = blockIdx.x * 128 + threadIdx.x;
    if (n >= NP) return;
    float x = r[2 * n], y = r[2 * n + 1];
    const float w0 = 0.6283185307179586f;   // 2*pi/10
    float s1x, c1x, s1y, c1y;
    sincosf(w0 * x, &s1x, &c1x);
    sincosf(w0 * y, &s1y, &c1y);

    unsigned long long xd[64];
    xd[0] = pk2(c1x, c1x);
    xd[1] = pk2(s1x, s1x);
    float cc = c1x, ss = s1x;
#pragma unroll
    for (int i = 1; i < 32; i++) {
        float nc = cc * c1x - ss * s1x;
        float ns = ss * c1x + cc * s1x;
        xd[2 * i] = pk2(nc, nc);
        xd[2 * i + 1] = pk2(ns, ns);
        cc = nc; ss = ns;
    }

    uint32_t mbase = (uint32_t)__cvta_generic_to_shared(&sM[0]);
    unsigned long long acc2 = pk2(0.f, 0.f);
    float cy = c1y, sy = s1y;
#pragma unroll 1
    for (int jq = 0; jq < 16; jq++) {
        float cy2 = cy * c1y - sy * s1y;
        float sy2 = sy * c1y + cy * s1y;
        unsigned long long t01 = pk2(0.f, 0.f), t23 = pk2(0.f, 0.f);
        uint32_t addr = mbase + jq * 16;
#pragma unroll
        for (int i = 0; i < 64; i++) {
            unsigned long long m01, m23;
            asm("ld.shared.v2.b64 {%0,%1}, [%2];"
                : "=l"(m01), "=l"(m23) : "r"(addr + i * 256));
            fma2(t01, m01, xd[i]);
            fma2(t23, m23, xd[i]);
        }
        fma2(acc2, t01, pk2(cy, sy));
        fma2(acc2, t23, pk2(cy2, sy2));
        float cy3 = cy2 * c1y - sy2 * s1y;
        float sy3 = sy2 * c1y + cy2 * s1y;
        cy = cy3; sy = sy3;
    }
    float lo, hi;
    asm("mov.b64 {%0,%1}, %2;" : "=f"(lo), "=f"(hi) : "l"(acc2));
    out[n] = g_bsum + lo + hi;
}

// ---------------- launcher --------------------------------------------------
extern "C" void kernel_launch(void* const* d_in, const int* in_sizes, int n_in,
                              void* d_out, int out_size) {
    const float* sources = (const float*)d_in[0];
    const float* r       = (const float*)d_in[1];
    const float* W1      = (const float*)d_in[2];
    const float* b1      = (const float*)d_in[3];
    const float* W2      = (const float*)d_in[4];
    const float* b2      = (const float*)d_in[5];
    const float* W3      = (const float*)d_in[6];
    const float* b3      = (const float*)d_in[7];
    const float* W4      = (const float*)d_in[8];
    const float* b4      = (const float*)d_in[9];
    const float* Wb      = (const float*)d_in[10];
    const float* bb      = (const float*)d_in[11];
    float* out = (float*)d_out;

    int S  = in_sizes[0] / 4;          // 2048
    int NP = out_size;                 // 100000

    k_prep<<<12289, 256>>>(sources, W1, b1, W2, W3, Wb, bb, S);

    dim3 gg(WDIM / 64, SMAX / 128);    // (16, 16) = 256 CTAs
    k_gemm<1><<<gg, 128>>>(b2);
    k_gemm<2><<<gg, 128>>>(b3);

    k_wsum<<<512, 256>>>(W4, b4, (float)S);

    int nb = (NP + 127) / 128;
    k_fourier<<<nb, 128>>>(r, out, NP);
}